// round 9
// baseline (speedup 1.0000x reference)
#include <cuda_runtime.h>

#define NTOK   4096
#define PDIM   128
#define HEADS  4
#define EDIM   32
#define NSEGS  32
#define KCAP   192
#define QT     64
#define QTILES 3
#define SSTR   66      // S row stride (key-major), R2 layout
#define QSCALE 0.17677669529663687f
#define NEGINF (-3.0e38f)
#define NBLK   256     // persistent blocks (<= 2/SM * 148 = 296 co-resident)
#define NQKV   384     // 64 x-tiles * 6 (mat*2+colh)
#define NATTN  384     // 32 segs * 4 heads * 3 qtiles

typedef unsigned long long ull;

__device__ float g_QKV[3][NTOK * PDIM];
__device__ int   g_idx[NTOK];
__device__ int   g_off[NSEGS + 1];
__device__ int   g_cnt[NSEGS];
__device__ int   g_q1, g_q2, g_b1, g_b2;   // tickets + barriers (reset by last block)

// f32x2 packed helpers (sm_103a FFMA2, PTX-only)
__device__ __forceinline__ ull f2pk(float lo, float hi) {
    ull r; asm("mov.b64 %0, {%1, %2};" : "=l"(r) : "f"(lo), "f"(hi)); return r;
}
__device__ __forceinline__ ull ffma2(ull a, ull b, ull c) {
    ull d; asm("fma.rn.f32x2 %0, %1, %2, %3;" : "=l"(d) : "l"(a), "l"(b), "l"(c)); return d;
}
__device__ __forceinline__ void f2un(ull v, float& lo, float& hi) {
    asm("mov.b64 {%0, %1}, %2;" : "=f"(lo), "=f"(hi) : "l"(v));
}

// ---------------------------------------------------------------------------
// Fused O(N) stable sort-by-segment (one block's worth of work)
// ---------------------------------------------------------------------------
__device__ void sort_block(const int* __restrict__ pos, int* sm) {
    int* spos    = sm;            // 4096
    int* hist    = sm + 4096;     // 4096
    int* warptot = sm + 8192;     // 8
    const int tid = threadIdx.x, lane = tid & 31, w = tid >> 5;

    const int4* pos4 = (const int4*)pos;
    int4 z4 = make_int4(0, 0, 0, 0);
    for (int i = tid; i < NTOK / 4; i += 256) {
        ((int4*)spos)[i] = pos4[i];
        ((int4*)hist)[i] = z4;
    }
    __syncthreads();

    for (int g = w; g < 128; g += 8) {
        int s = spos[g * 32 + lane];
        unsigned mask = __match_any_sync(0xffffffffu, s);
        if (lane == __ffs(mask) - 1) hist[s * 128 + g] = __popc(mask);
    }
    __syncthreads();

    int base = tid * 16;
    int loc[16];
    int run = 0;
#pragma unroll
    for (int i = 0; i < 16; i++) { loc[i] = run; run += hist[base + i]; }
    int s = run;
#pragma unroll
    for (int d = 1; d < 32; d <<= 1) {
        int o = __shfl_up_sync(0xffffffffu, s, d);
        if (lane >= d) s += o;
    }
    int excl = s - run;
    if (lane == 31) warptot[w] = s;
    __syncthreads();
    if (tid == 0) {
        int a = 0;
#pragma unroll
        for (int i = 0; i < 8; i++) { int t = warptot[i]; warptot[i] = a; a += t; }
    }
    __syncthreads();
    int offt = warptot[w] + excl;
#pragma unroll
    for (int i = 0; i < 16; i++) hist[base + i] = offt + loc[i];
    __syncthreads();

    if (tid < NSEGS) {
        int o   = hist[tid * 128];
        int nxt = (tid == NSEGS - 1) ? NTOK : hist[(tid + 1) * 128];
        g_off[tid] = o;
        g_cnt[tid] = nxt - o;
        if (tid == 0) g_off[NSEGS] = NTOK;
    }

    for (int g = w; g < 128; g += 8) {
        int tok = g * 32 + lane;
        int sg = spos[tok];
        unsigned mask = __match_any_sync(0xffffffffu, sg);
        int rank = __popc(mask & ((1u << lane) - 1u));
        g_idx[hist[sg * 128 + g] + rank] = tok;
    }
}

// ---------------------------------------------------------------------------
// QKV 64x64 tile (R2-exact body). item: x = it & 63, y = it >> 6 (mat*2+colh)
// ---------------------------------------------------------------------------
__device__ void qkv_tile(int item, float* sm,
                         const float* __restrict__ inp,
                         const float* __restrict__ Wq, const float* __restrict__ bq,
                         const float* __restrict__ Wk, const float* __restrict__ bk,
                         const float* __restrict__ Wv, const float* __restrict__ bv)
{
    float* As = sm;               // 64 x 128
    float* Bs = sm + 64 * PDIM;   // 128 x 64

    const int x = item & 63, y = item >> 6;
    const int which = y >> 1, colh = y & 1;
    const float* W = (which == 0) ? Wq : (which == 1) ? Wk : Wv;
    const float* b = (which == 0) ? bq : (which == 1) ? bk : bv;
    float* outp = g_QKV[which];

    const int row0 = x * 64, col0 = colh * 64;
    const int tid = threadIdx.x;

    const float4* inp4 = (const float4*)(inp + row0 * PDIM);
    const float4* W4 = (const float4*)W;
    for (int i = tid; i < 2048; i += 256) ((float4*)As)[i] = inp4[i];
    for (int i = tid; i < 2048; i += 256) {
        int k = i >> 4, c4 = i & 15;
        ((float4*)Bs)[k * 16 + c4] = W4[k * 32 + colh * 16 + c4];
    }
    __syncthreads();

    const int tx = tid & 15, ty = tid >> 4;

    ull acc[4][2];
#pragma unroll
    for (int i = 0; i < 4; i++) { acc[i][0] = 0ull; acc[i][1] = 0ull; }

    const ulonglong2* Bs2 = (const ulonglong2*)Bs;
#pragma unroll 2
    for (int k = 0; k < PDIM; k++) {
        ulonglong2 bb = Bs2[k * 16 + tx];
#pragma unroll
        for (int i = 0; i < 4; i++) {
            float a = As[(ty * 4 + i) * PDIM + k];
            ull aa = f2pk(a, a);
            acc[i][0] = ffma2(aa, bb.x, acc[i][0]);
            acc[i][1] = ffma2(aa, bb.y, acc[i][1]);
        }
    }

    float4 bias = ((const float4*)(b + col0))[tx];
    float4* out4 = (float4*)outp;
#pragma unroll
    for (int i = 0; i < 4; i++) {
        int row = row0 + ty * 4 + i;
        float x0, x1, x2, x3;
        f2un(acc[i][0], x0, x1);
        f2un(acc[i][1], x2, x3);
        out4[row * 32 + colh * 16 + tx] =
            make_float4(x0 + bias.x, x1 + bias.y, x2 + bias.z, x3 + bias.w);
    }
}

// ---------------------------------------------------------------------------
// Attention item (R2-exact body). item: seg = it&31, h = (it>>5)&3, z = it>>7
// SMEM: KT[32][192] Vs[192][32] QsT[32][64] S[192][66] sInv[64] = 108288 B
// ---------------------------------------------------------------------------
__device__ void attn_item(int item, float* smf, float* __restrict__ out)
{
    float* KT   = smf;                        // 32*KCAP
    float* Vs   = KT + EDIM * KCAP;           // KCAP*32
    float* QsT  = Vs + KCAP * EDIM;           // 32*QT
    float* S    = QsT + EDIM * QT;            // KCAP*SSTR (key-major)
    float* sInv = S + KCAP * SSTR;            // QT

    const int seg = item & 31, h = (item >> 5) & 3, z = item >> 7;
    const int off = g_off[seg];
    const int cnt = g_cnt[seg];
    const int tid = threadIdx.x, lane = tid & 31, w = tid >> 5;

    const float* Q = g_QKV[0];
    const float* K = g_QKV[1];
    const float* V = g_QKV[2];

    if (cnt > KCAP) {
        // fallback: streaming online softmax (uniform per block)
        int gw = z * 8 + w;
        for (int qi = gw; qi < cnt; qi += QTILES * 8) {
            int t = g_idx[off + qi];
            float qv = Q[t * PDIM + h * EDIM + lane] * QSCALE;
            float m = NEGINF, l = 0.f, a = 0.f;
            for (int j = 0; j < cnt; j++) {
                int tj = g_idx[off + j];
                float s = qv * K[tj * PDIM + h * EDIM + lane];
#pragma unroll
                for (int d = 16; d; d >>= 1) s += __shfl_xor_sync(0xffffffffu, s, d);
                float mn  = fmaxf(m, s);
                float cor = __expf(m - mn);
                float pj  = __expf(s - mn);
                l = l * cor + pj;
                a = a * cor + pj * V[tj * PDIM + h * EDIM + lane];
                m = mn;
            }
            out[t * PDIM + h * EDIM + lane] = a / l;
        }
        return;
    }

    const int nq = min(QT, cnt - z * QT);
    if (nq <= 0) return;

    // gather K (transposed) + V
    for (int i = tid; i < cnt * 8; i += 256) {
        int r = i >> 3, c = i & 7;
        int t = g_idx[off + r];
        float4 kf = *(const float4*)(K + t * PDIM + h * EDIM + c * 4);
        KT[(c * 4 + 0) * KCAP + r] = kf.x;
        KT[(c * 4 + 1) * KCAP + r] = kf.y;
        KT[(c * 4 + 2) * KCAP + r] = kf.z;
        KT[(c * 4 + 3) * KCAP + r] = kf.w;
        *(float4*)&Vs[r * EDIM + c * 4] = *(const float4*)(V + t * PDIM + h * EDIM + c * 4);
    }
    // gather Q tile (transposed, pre-scaled)
    for (int i = tid; i < nq * 8; i += 256) {
        int q = i >> 3, c = i & 7;
        int t = g_idx[off + z * QT + q];
        float4 qf = *(const float4*)(Q + t * PDIM + h * EDIM + c * 4);
        QsT[(c * 4 + 0) * QT + q] = qf.x * QSCALE;
        QsT[(c * 4 + 1) * QT + q] = qf.y * QSCALE;
        QsT[(c * 4 + 2) * QT + q] = qf.z * QSCALE;
        QsT[(c * 4 + 3) * QT + q] = qf.w * QSCALE;
    }
    __syncthreads();

    const int tx = tid & 15, ty = tid >> 4;

    // ---- GEMM1: S[j][q] = sum_e Q[q][e]*K[j][e]  (pairs along q) ----
    {
        ull acc[2][12];
#pragma unroll
        for (int r = 0; r < 12; r++) { acc[0][r] = 0ull; acc[1][r] = 0ull; }

#pragma unroll 2
        for (int e = 0; e < EDIM; e++) {
            const float* KTe = KT + e * KCAP + tx;
            float2 qa = *(const float2*)&QsT[e * QT + ty * 4];
            float2 qb = *(const float2*)&QsT[e * QT + ty * 4 + 2];
            ull qpa = f2pk(qa.x, qa.y);
            ull qpb = f2pk(qb.x, qb.y);
#pragma unroll
            for (int r = 0; r < 12; r++) {
                float kv = KTe[16 * r];
                ull kk = f2pk(kv, kv);
                acc[0][r] = ffma2(qpa, kk, acc[0][r]);
                acc[1][r] = ffma2(qpb, kk, acc[1][r]);
            }
        }
#pragma unroll
        for (int r = 0; r < 12; r++) {
            int j = tx + 16 * r;
            *(ull*)&S[j * SSTR + ty * 4]     = acc[0][r];
            *(ull*)&S[j * SSTR + ty * 4 + 2] = acc[1][r];
        }
    }
    __syncthreads();

    // ---- softmax over keys per query (deferred normalization) ----
    for (int q = w; q < nq; q += 8) {
        float m = NEGINF;
        for (int j = lane; j < cnt; j += 32) m = fmaxf(m, S[j * SSTR + q]);
#pragma unroll
        for (int d = 16; d; d >>= 1) m = fmaxf(m, __shfl_xor_sync(0xffffffffu, m, d));
        float sum = 0.f;
        for (int j = lane; j < cnt; j += 32) {
            float p = __expf(S[j * SSTR + q] - m);
            S[j * SSTR + q] = p;
            sum += p;
        }
#pragma unroll
        for (int d = 16; d; d >>= 1) sum += __shfl_xor_sync(0xffffffffu, sum, d);
        if (lane == 0) sInv[q] = 1.f / sum;
    }
    __syncthreads();

    // ---- GEMM2: O[q][e] = sum_j P[j][q]*V[j][e]  (pairs along q) ----
    ull o00 = 0ull, o01 = 0ull, o10 = 0ull, o11 = 0ull;
#pragma unroll 4
    for (int j = 0; j < cnt; j++) {
        ull ppa = *(const ull*)&S[j * SSTR + ty * 4];
        ull ppb = *(const ull*)&S[j * SSTR + ty * 4 + 2];
        float2 v = *(const float2*)&Vs[j * EDIM + tx * 2];
        ull v0 = f2pk(v.x, v.x);
        ull v1 = f2pk(v.y, v.y);
        o00 = ffma2(ppa, v0, o00);
        o01 = ffma2(ppa, v1, o01);
        o10 = ffma2(ppb, v0, o10);
        o11 = ffma2(ppb, v1, o11);
    }

    // ---- epilogue ----
    {
        int e0 = h * EDIM + tx * 2;
        float a0e0, a1e0, a0e1, a1e1;
        f2un(o00, a0e0, a1e0);
        f2un(o01, a0e1, a1e1);
        int qa = ty * 4, qb = ty * 4 + 1;
        if (qa < nq) {
            int t = g_idx[off + z * QT + qa]; float iv = sInv[qa];
            out[t * PDIM + e0] = a0e0 * iv; out[t * PDIM + e0 + 1] = a0e1 * iv;
        }
        if (qb < nq) {
            int t = g_idx[off + z * QT + qb]; float iv = sInv[qb];
            out[t * PDIM + e0] = a1e0 * iv; out[t * PDIM + e0 + 1] = a1e1 * iv;
        }
        f2un(o10, a0e0, a1e0);
        f2un(o11, a0e1, a1e1);
        qa = ty * 4 + 2; qb = ty * 4 + 3;
        if (qa < nq) {
            int t = g_idx[off + z * QT + qa]; float iv = sInv[qa];
            out[t * PDIM + e0] = a0e0 * iv; out[t * PDIM + e0 + 1] = a0e1 * iv;
        }
        if (qb < nq) {
            int t = g_idx[off + z * QT + qb]; float iv = sInv[qb];
            out[t * PDIM + e0] = a1e0 * iv; out[t * PDIM + e0 + 1] = a1e1 * iv;
        }
    }
}

// ---------------------------------------------------------------------------
// Persistent fused kernel: ticket-queue QKV+sort -> device barrier -> attn.
// 256 blocks co-resident (2/SM at 108 KB smem) -> barrier is deadlock-free.
// Last block resets counters so the kernel is graph-replay idempotent.
// ---------------------------------------------------------------------------
__global__ __launch_bounds__(256, 2)
void fused_kernel(const float* __restrict__ inp, const int* __restrict__ pos,
                  const float* __restrict__ Wq, const float* __restrict__ bq,
                  const float* __restrict__ Wk, const float* __restrict__ bk,
                  const float* __restrict__ Wv, const float* __restrict__ bv,
                  float* __restrict__ out)
{
    extern __shared__ float sm[];
    __shared__ int sT;
    const int tid = threadIdx.x;

    // ---- Phase A: QKV tiles + sort, dynamically balanced ----
    for (;;) {
        if (tid == 0) sT = atomicAdd(&g_q1, 1);
        __syncthreads();
        int it = sT;
        if (it >= NQKV + 1) break;
        if (it < NQKV) qkv_tile(it, sm, inp, Wq, bq, Wk, bk, Wv, bv);
        else           sort_block(pos, (int*)sm);
    }

    // ---- device-wide barrier ----
    if (tid == 0) {
        __threadfence();
        atomicAdd(&g_b1, 1);
        while (*(volatile int*)&g_b1 < NBLK) { }
        __threadfence();
    }
    __syncthreads();

    // ---- Phase B: attention items (heavy z=0,1 first in ticket order) ----
    for (;;) {
        if (tid == 0) sT = atomicAdd(&g_q2, 1);
        __syncthreads();
        int it = sT;
        if (it >= NATTN) break;
        attn_item(it, sm, out);
    }

    // ---- finish: last block resets counters for the next graph replay ----
    if (tid == 0) {
        __threadfence();
        int r = atomicAdd(&g_b2, 1);
        if (r == NBLK - 1) {
            g_q1 = 0; g_q2 = 0; g_b1 = 0; g_b2 = 0;
            __threadfence();
        }
    }
}

// ---------------------------------------------------------------------------
extern "C" void kernel_launch(void* const* d_in, const int* in_sizes, int n_in,
                              void* d_out, int out_size)
{
    const float* inp = (const float*)d_in[0];
    const int*   pos = (const int*)  d_in[1];
    const float* Wq  = (const float*)d_in[2];
    const float* bq  = (const float*)d_in[3];
    const float* Wk  = (const float*)d_in[4];
    const float* bk  = (const float*)d_in[5];
    const float* Wv  = (const float*)d_in[6];
    const float* bv  = (const float*)d_in[7];
    float* out = (float*)d_out;

    const int smem = (EDIM * KCAP + KCAP * EDIM + EDIM * QT
                      + KCAP * SSTR + QT) * 4;   // 108288 (>= qkv's 65536)

    cudaFuncSetAttribute(fused_kernel, cudaFuncAttributeMaxDynamicSharedMemorySize, smem);
    fused_kernel<<<NBLK, 256, smem>>>(inp, pos, Wq, bq, Wk, bk, Wv, bv, out);
}

// round 10
// speedup vs baseline: 1.3097x; 1.3097x over previous
#include <cuda_runtime.h>

#define NTOK   4096
#define PDIM   128
#define HEADS  4
#define EDIM   32
#define NSEGS  32
#define KCAP   192     // max segment rows on the fast path
#define QT     64      // queries per attention block
#define QTILES 3
#define SSTR   66      // S row stride (key-major)
#define QSCALE 0.17677669529663687f
#define NEGINF (-3.0e38f)

typedef unsigned long long ull;

__device__ float g_QKV[3][NTOK * PDIM];
__device__ int   g_idx[NTOK];
__device__ int   g_off[NSEGS + 1];
__device__ int   g_cnt[NSEGS];

// f32x2 packed helpers (sm_103a FFMA2, PTX-only)
__device__ __forceinline__ ull f2pk(float lo, float hi) {
    ull r; asm("mov.b64 %0, {%1, %2};" : "=l"(r) : "f"(lo), "f"(hi)); return r;
}
__device__ __forceinline__ ull ffma2(ull a, ull b, ull c) {
    ull d; asm("fma.rn.f32x2 %0, %1, %2, %3;" : "=l"(d) : "l"(a), "l"(b), "l"(c)); return d;
}
__device__ __forceinline__ void f2un(ull v, float& lo, float& hi) {
    asm("mov.b64 {%0, %1}, %2;" : "=f"(lo), "=f"(hi) : "l"(v));
}

// ---------------------------------------------------------------------------
// Fused O(N) stable sort-by-segment (one block, 256 threads)   [R2 verbatim]
// ---------------------------------------------------------------------------
__device__ void sort_block(const int* __restrict__ pos, int* sm) {
    int* spos    = sm;            // 4096
    int* hist    = sm + 4096;     // 4096
    int* warptot = sm + 8192;     // 8
    const int tid = threadIdx.x, lane = tid & 31, w = tid >> 5;

    const int4* pos4 = (const int4*)pos;
    int4 z4 = make_int4(0, 0, 0, 0);
    for (int i = tid; i < NTOK / 4; i += 256) {
        ((int4*)spos)[i] = pos4[i];
        ((int4*)hist)[i] = z4;
    }
    __syncthreads();

    for (int g = w; g < 128; g += 8) {
        int s = spos[g * 32 + lane];
        unsigned mask = __match_any_sync(0xffffffffu, s);
        if (lane == __ffs(mask) - 1) hist[s * 128 + g] = __popc(mask);
    }
    __syncthreads();

    int base = tid * 16;
    int loc[16];
    int run = 0;
#pragma unroll
    for (int i = 0; i < 16; i++) { loc[i] = run; run += hist[base + i]; }
    int s = run;
#pragma unroll
    for (int d = 1; d < 32; d <<= 1) {
        int o = __shfl_up_sync(0xffffffffu, s, d);
        if (lane >= d) s += o;
    }
    int excl = s - run;
    if (lane == 31) warptot[w] = s;
    __syncthreads();
    if (tid == 0) {
        int a = 0;
#pragma unroll
        for (int i = 0; i < 8; i++) { int t = warptot[i]; warptot[i] = a; a += t; }
    }
    __syncthreads();
    int offt = warptot[w] + excl;
#pragma unroll
    for (int i = 0; i < 16; i++) hist[base + i] = offt + loc[i];
    __syncthreads();

    if (tid < NSEGS) {
        int o   = hist[tid * 128];
        int nxt = (tid == NSEGS - 1) ? NTOK : hist[(tid + 1) * 128];
        g_off[tid] = o;
        g_cnt[tid] = nxt - o;
        if (tid == 0) g_off[NSEGS] = NTOK;
    }

    for (int g = w; g < 128; g += 8) {
        int tok = g * 32 + lane;
        int sg = spos[tok];
        unsigned mask = __match_any_sync(0xffffffffu, sg);
        int rank = __popc(mask & ((1u << lane) - 1u));
        g_idx[hist[sg * 128 + g] + rank] = tok;
    }
}

// ---------------------------------------------------------------------------
// QKV projection + fused sort. grid (65, 6). 64x64 tiles.   [R2 verbatim]
// ---------------------------------------------------------------------------
__global__ __launch_bounds__(256)
void qkv_sort_kernel(const float* __restrict__ inp, const int* __restrict__ pos,
                     const float* __restrict__ Wq, const float* __restrict__ bq,
                     const float* __restrict__ Wk, const float* __restrict__ bk,
                     const float* __restrict__ Wv, const float* __restrict__ bv)
{
    extern __shared__ float sm[];
    if (blockIdx.x == 64) {
        if (blockIdx.y == 0) sort_block(pos, (int*)sm);
        return;
    }

    float* As = sm;               // 64 x 128
    float* Bs = sm + 64 * PDIM;   // 128 x 64

    const int which = blockIdx.y >> 1, colh = blockIdx.y & 1;
    const float* W = (which == 0) ? Wq : (which == 1) ? Wk : Wv;
    const float* b = (which == 0) ? bq : (which == 1) ? bk : bv;
    float* outp = g_QKV[which];

    const int row0 = blockIdx.x * 64, col0 = colh * 64;
    const int tid = threadIdx.x;

    const float4* inp4 = (const float4*)(inp + row0 * PDIM);
    const float4* W4 = (const float4*)W;
    for (int i = tid; i < 2048; i += 256) ((float4*)As)[i] = inp4[i];
    for (int i = tid; i < 2048; i += 256) {
        int k = i >> 4, c4 = i & 15;
        ((float4*)Bs)[k * 16 + c4] = W4[k * 32 + colh * 16 + c4];
    }
    __syncthreads();

    const int tx = tid & 15, ty = tid >> 4;

    ull acc[4][2];
#pragma unroll
    for (int i = 0; i < 4; i++) { acc[i][0] = 0ull; acc[i][1] = 0ull; }

    const ulonglong2* Bs2 = (const ulonglong2*)Bs;
#pragma unroll 2
    for (int k = 0; k < PDIM; k++) {
        ulonglong2 bb = Bs2[k * 16 + tx];
#pragma unroll
        for (int i = 0; i < 4; i++) {
            float a = As[(ty * 4 + i) * PDIM + k];
            ull aa = f2pk(a, a);
            acc[i][0] = ffma2(aa, bb.x, acc[i][0]);
            acc[i][1] = ffma2(aa, bb.y, acc[i][1]);
        }
    }

    float4 bias = ((const float4*)(b + col0))[tx];
    float4* out4 = (float4*)outp;
#pragma unroll
    for (int i = 0; i < 4; i++) {
        int row = row0 + ty * 4 + i;
        float x0, x1, x2, x3;
        f2un(acc[i][0], x0, x1);
        f2un(acc[i][1], x2, x3);
        out4[row * 32 + colh * 16 + tx] =
            make_float4(x0 + bias.x, x1 + bias.y, x2 + bias.z, x3 + bias.w);
    }
}

// ---------------------------------------------------------------------------
// Attention per (seg, head, 64-query tile). 256 threads, 2 blocks/SM.
// R2 structure; ONLY GEMM1's thread map changed: 8 queries x 6 keys per
// thread (each K scalar feeds 4 FFMA2; Q loads are warp-uniform broadcasts).
// SMEM: KT[32][192] Vs[192][32] QsT[32][64] S[192][66] sInv[64] = 108288 B
// ---------------------------------------------------------------------------
__global__ __launch_bounds__(256, 2)
void attn_kernel(float* __restrict__ out)
{
    extern __shared__ float smf[];
    float* KT   = smf;                        // 32*KCAP
    float* Vs   = KT + EDIM * KCAP;           // KCAP*32
    float* QsT  = Vs + KCAP * EDIM;           // 32*QT
    float* S    = QsT + EDIM * QT;            // KCAP*SSTR (key-major)
    float* sInv = S + KCAP * SSTR;            // QT

    const int seg = blockIdx.x, h = blockIdx.y, z = blockIdx.z;
    const int off = g_off[seg];
    const int cnt = g_cnt[seg];
    const int tid = threadIdx.x, lane = tid & 31, w = tid >> 5;

    const float* Q = g_QKV[0];
    const float* K = g_QKV[1];
    const float* V = g_QKV[2];

    if (cnt > KCAP) {
        // fallback: streaming online softmax (correct for any count)
        int gw = z * 8 + w;
        for (int qi = gw; qi < cnt; qi += QTILES * 8) {
            int t = g_idx[off + qi];
            float qv = Q[t * PDIM + h * EDIM + lane] * QSCALE;
            float m = NEGINF, l = 0.f, a = 0.f;
            for (int j = 0; j < cnt; j++) {
                int tj = g_idx[off + j];
                float s = qv * K[tj * PDIM + h * EDIM + lane];
#pragma unroll
                for (int d = 16; d; d >>= 1) s += __shfl_xor_sync(0xffffffffu, s, d);
                float mn  = fmaxf(m, s);
                float cor = __expf(m - mn);
                float pj  = __expf(s - mn);
                l = l * cor + pj;
                a = a * cor + pj * V[tj * PDIM + h * EDIM + lane];
                m = mn;
            }
            out[t * PDIM + h * EDIM + lane] = a / l;
        }
        return;
    }

    const int nq = min(QT, cnt - z * QT);
    if (nq <= 0) return;

    // gather K (transposed) + V   [R2 verbatim]
    for (int i = tid; i < cnt * 8; i += 256) {
        int r = i >> 3, c = i & 7;
        int t = g_idx[off + r];
        float4 kf = *(const float4*)(K + t * PDIM + h * EDIM + c * 4);
        KT[(c * 4 + 0) * KCAP + r] = kf.x;
        KT[(c * 4 + 1) * KCAP + r] = kf.y;
        KT[(c * 4 + 2) * KCAP + r] = kf.z;
        KT[(c * 4 + 3) * KCAP + r] = kf.w;
        *(float4*)&Vs[r * EDIM + c * 4] = *(const float4*)(V + t * PDIM + h * EDIM + c * 4);
    }
    // gather Q tile (transposed, pre-scaled)   [R2 verbatim]
    for (int i = tid; i < nq * 8; i += 256) {
        int q = i >> 3, c = i & 7;
        int t = g_idx[off + z * QT + q];
        float4 qf = *(const float4*)(Q + t * PDIM + h * EDIM + c * 4);
        QsT[(c * 4 + 0) * QT + q] = qf.x * QSCALE;
        QsT[(c * 4 + 1) * QT + q] = qf.y * QSCALE;
        QsT[(c * 4 + 2) * QT + q] = qf.z * QSCALE;
        QsT[(c * 4 + 3) * QT + q] = qf.w * QSCALE;
    }
    __syncthreads();

    // ---- GEMM1: S[j][q] = sum_e Q[q][e]*K[j][e]  (pairs along q) ----
    // NEW MAP: kx = tid&31 -> keys {kx+32r, r=0..5}; qy = tid>>5 -> queries
    // qy*8 + 2i + {0,1}, i=0..3.  Q loads warp-uniform; K loads 1 phase each.
    {
        const int kx = tid & 31, qy = tid >> 5;
        ull acc[4][6];
#pragma unroll
        for (int i = 0; i < 4; i++)
#pragma unroll
            for (int r = 0; r < 6; r++) acc[i][r] = 0ull;

#pragma unroll 2
        for (int e = 0; e < EDIM; e++) {
            const float* qe  = QsT + e * QT + qy * 8;
            ull qp[4];
#pragma unroll
            for (int i = 0; i < 4; i++) {
                float2 qv = *(const float2*)(qe + 2 * i);   // warp-uniform broadcast
                qp[i] = f2pk(qv.x, qv.y);
            }
            const float* kte = KT + e * KCAP + kx;
#pragma unroll
            for (int r = 0; r < 6; r++) {
                float kv = kte[32 * r];                     // 32 distinct banks, 1 phase
                ull kk = f2pk(kv, kv);
                acc[0][r] = ffma2(qp[0], kk, acc[0][r]);
                acc[1][r] = ffma2(qp[1], kk, acc[1][r]);
                acc[2][r] = ffma2(qp[2], kk, acc[2][r]);
                acc[3][r] = ffma2(qp[3], kk, acc[3][r]);
            }
        }
#pragma unroll
        for (int r = 0; r < 6; r++) {
            float* srow = S + (kx + 32 * r) * SSTR + qy * 8;
#pragma unroll
            for (int i = 0; i < 4; i++)
                *(ull*)(srow + 2 * i) = acc[i][r];          // CF per half-warp
        }
    }
    __syncthreads();

    // ---- softmax over keys per query (deferred normalization)  [R2 verbatim] ----
    for (int q = w; q < nq; q += 8) {
        float m = NEGINF;
        for (int j = lane; j < cnt; j += 32) m = fmaxf(m, S[j * SSTR + q]);
#pragma unroll
        for (int d = 16; d; d >>= 1) m = fmaxf(m, __shfl_xor_sync(0xffffffffu, m, d));
        float sum = 0.f;
        for (int j = lane; j < cnt; j += 32) {
            float p = __expf(S[j * SSTR + q] - m);
            S[j * SSTR + q] = p;
            sum += p;
        }
#pragma unroll
        for (int d = 16; d; d >>= 1) sum += __shfl_xor_sync(0xffffffffu, sum, d);
        if (lane == 0) sInv[q] = 1.f / sum;
    }
    __syncthreads();

    // ---- GEMM2: O[q][e] = sum_j P[j][q]*V[j][e]  (pairs along q)  [R2 verbatim] ----
    const int tx = tid & 15, ty = tid >> 4;
    ull o00 = 0ull, o01 = 0ull, o10 = 0ull, o11 = 0ull;
#pragma unroll 4
    for (int j = 0; j < cnt; j++) {
        ull ppa = *(const ull*)&S[j * SSTR + ty * 4];
        ull ppb = *(const ull*)&S[j * SSTR + ty * 4 + 2];
        float2 v = *(const float2*)&Vs[j * EDIM + tx * 2];
        ull v0 = f2pk(v.x, v.x);
        ull v1 = f2pk(v.y, v.y);
        o00 = ffma2(ppa, v0, o00);
        o01 = ffma2(ppa, v1, o01);
        o10 = ffma2(ppb, v0, o10);
        o11 = ffma2(ppb, v1, o11);
    }

    // ---- epilogue  [R2 verbatim] ----
    {
        int e0 = h * EDIM + tx * 2;
        float a0e0, a1e0, a0e1, a1e1;
        f2un(o00, a0e0, a1e0);
        f2un(o01, a0e1, a1e1);
        int qa = ty * 4, qb = ty * 4 + 1;
        if (qa < nq) {
            int t = g_idx[off + z * QT + qa]; float iv = sInv[qa];
            out[t * PDIM + e0] = a0e0 * iv; out[t * PDIM + e0 + 1] = a0e1 * iv;
        }
        if (qb < nq) {
            int t = g_idx[off + z * QT + qb]; float iv = sInv[qb];
            out[t * PDIM + e0] = a1e0 * iv; out[t * PDIM + e0 + 1] = a1e1 * iv;
        }
        f2un(o10, a0e0, a1e0);
        f2un(o11, a0e1, a1e1);
        qa = ty * 4 + 2; qb = ty * 4 + 3;
        if (qa < nq) {
            int t = g_idx[off + z * QT + qa]; float iv = sInv[qa];
            out[t * PDIM + e0] = a0e0 * iv; out[t * PDIM + e0 + 1] = a0e1 * iv;
        }
        if (qb < nq) {
            int t = g_idx[off + z * QT + qb]; float iv = sInv[qb];
            out[t * PDIM + e0] = a1e0 * iv; out[t * PDIM + e0 + 1] = a1e1 * iv;
        }
    }
}

// ---------------------------------------------------------------------------
extern "C" void kernel_launch(void* const* d_in, const int* in_sizes, int n_in,
                              void* d_out, int out_size)
{
    const float* inp = (const float*)d_in[0];
    const int*   pos = (const int*)  d_in[1];
    const float* Wq  = (const float*)d_in[2];
    const float* bq  = (const float*)d_in[3];
    const float* Wk  = (const float*)d_in[4];
    const float* bk  = (const float*)d_in[5];
    const float* Wv  = (const float*)d_in[6];
    const float* bv  = (const float*)d_in[7];
    float* out = (float*)d_out;

    const int qkv_smem  = (64 * PDIM + PDIM * 64) * 4;                           // 65536
    const int attn_smem = (EDIM * KCAP + KCAP * EDIM + EDIM * QT
                           + KCAP * SSTR + QT) * 4;                              // 108288

    cudaFuncSetAttribute(qkv_sort_kernel, cudaFuncAttributeMaxDynamicSharedMemorySize, qkv_smem);
    cudaFuncSetAttribute(attn_kernel,     cudaFuncAttributeMaxDynamicSharedMemorySize, attn_smem);

    qkv_sort_kernel<<<dim3(65, 6), 256, qkv_smem>>>(inp, pos, Wq, bq, Wk, bk, Wv, bv);
    attn_kernel<<<dim3(NSEGS, HEADS, QTILES), 256, attn_smem>>>(out);
}